// round 6
// baseline (speedup 1.0000x reference)
#include <cuda_runtime.h>
#include <cstdint>
#include <math.h>

#define DEPTH 12
#define DIM   768
#define NH    12
#define HD    64
#define NTOK  577
#define BATCH 8
#define HID   3072
#define NCLS  1000
#define NPATCH 576
#define ROWS  (BATCH * NTOK)      // 4616
#define QKVW  (3 * DIM)           // 2304

// ---------------- scratch (device globals; allocation-free) ----------------
__device__ float g_h[ROWS * DIM];
__device__ float g_qkv[ROWS * QKVW];
__device__ float g_o[ROWS * DIM];
__device__ float g_mid[ROWS * HID];
__device__ float g_patches[BATCH * NPATCH * DIM];
__device__ float g_tmp[BATCH * NPATCH * DIM];
__device__ float g_lnm[ROWS];            // per-row LN mean
__device__ float g_lnr[ROWS];            // per-row LN rstd
__device__ float g_cls[BATCH * DIM];     // final-LN cls rows
// transposed weights, [N][K] per layer (B operand of mma row.col is K-major)
__device__ float g_qkvT[DEPTH * QKVW * DIM];
__device__ float g_projT[DEPTH * DIM * DIM];
__device__ float g_w1T[DEPTH * HID * DIM];
__device__ float g_w2T[DEPTH * DIM * HID];

// ====================== tf32 mma.sync GEMM =================================
#define SMS 36                    // smem row stride (floats): 32 + 4 pad
#define TILE_F (128 * SMS)
#define GEMM_SMEM (4 * TILE_F * 4)  // 73728 B

__device__ __forceinline__ uint32_t cvt_tf32(float f) {
    uint32_t u;
    asm("cvt.rna.tf32.f32 %0, %1;" : "=r"(u) : "f"(f));
    return u;
}

__device__ __forceinline__ void mma_tf32(float* c, const uint32_t* a, const uint32_t* b) {
    asm volatile(
        "mma.sync.aligned.m16n8k8.row.col.f32.tf32.tf32.f32 "
        "{%0,%1,%2,%3}, {%4,%5,%6,%7}, {%8,%9}, {%0,%1,%2,%3};"
        : "+f"(c[0]), "+f"(c[1]), "+f"(c[2]), "+f"(c[3])
        : "r"(a[0]), "r"(a[1]), "r"(a[2]), "r"(a[3]), "r"(b[0]), "r"(b[1]));
}

// LNA: apply (a - mean[row]) * rstd[row] * gamma[k] + beta[k] to A during load
template <bool LNA>
__device__ __forceinline__ void load_chunk_g(const float* __restrict__ A,
                                             const float* __restrict__ BT,
                                             const float* __restrict__ lnG,
                                             const float* __restrict__ lnB,
                                             int M, int K, int row0, int col0,
                                             int k0, float* dA, float* dB, int tid) {
    float4 va[4], vb[4];
#pragma unroll
    for (int i = 0; i < 4; i++) {
        int f4 = tid + i * 256;
        int r = f4 >> 3, cc = (f4 & 7) * 4;
        int gr = row0 + r;
        va[i] = make_float4(0.f, 0.f, 0.f, 0.f);
        if (gr < M) {
            va[i] = *(const float4*)(A + (size_t)gr * K + k0 + cc);
            if (LNA) {
                float mm = g_lnm[gr], rr = g_lnr[gr];
                float4 gam = *(const float4*)(lnG + k0 + cc);
                float4 bet = *(const float4*)(lnB + k0 + cc);
                va[i].x = (va[i].x - mm) * rr * gam.x + bet.x;
                va[i].y = (va[i].y - mm) * rr * gam.y + bet.y;
                va[i].z = (va[i].z - mm) * rr * gam.z + bet.z;
                va[i].w = (va[i].w - mm) * rr * gam.w + bet.w;
            }
        }
        vb[i] = *(const float4*)(BT + (size_t)(col0 + r) * K + k0 + cc);
    }
#pragma unroll
    for (int i = 0; i < 4; i++) {
        int f4 = tid + i * 256;
        int r = f4 >> 3, cc = (f4 & 7) * 4;
        float4 ca, cb;
        ca.x = __uint_as_float(cvt_tf32(va[i].x));
        ca.y = __uint_as_float(cvt_tf32(va[i].y));
        ca.z = __uint_as_float(cvt_tf32(va[i].z));
        ca.w = __uint_as_float(cvt_tf32(va[i].w));
        cb.x = __uint_as_float(cvt_tf32(vb[i].x));
        cb.y = __uint_as_float(cvt_tf32(vb[i].y));
        cb.z = __uint_as_float(cvt_tf32(vb[i].z));
        cb.w = __uint_as_float(cvt_tf32(vb[i].w));
        *(float4*)&dA[r * SMS + cc] = ca;
        *(float4*)&dB[r * SMS + cc] = cb;
    }
}

// EPI: 0 = bias, 1 = bias+GELU(exact), 2 = bias+residual
template <int EPI, bool LNA>
__global__ void __launch_bounds__(256, 2)
gemm_mma(const float* __restrict__ A, const float* __restrict__ BT,
         const float* __restrict__ bias, const float* __restrict__ res,
         const float* __restrict__ lnG, const float* __restrict__ lnB,
         float* __restrict__ C, int M, int N, int K) {
    extern __shared__ float sm[];
    float* As = sm;
    float* Bs = sm + 2 * TILE_F;
    const int tid = threadIdx.x;
    const int w = tid >> 5, lane = tid & 31;
    const int g = lane >> 2, t = lane & 3;
    const int warp_m = (w & 1) * 64, warp_n = (w >> 1) * 32;
    const int row0 = blockIdx.y * 128, col0 = blockIdx.x * 128;

    float acc[4][4][4] = {};
    const int NC = K / 32;

    load_chunk_g<LNA>(A, BT, lnG, lnB, M, K, row0, col0, 0, As, Bs, tid);
    __syncthreads();

    for (int ch = 0; ch < NC; ch++) {
        int buf = ch & 1;
        if (ch + 1 < NC)
            load_chunk_g<LNA>(A, BT, lnG, lnB, M, K, row0, col0, (ch + 1) * 32,
                              As + (buf ^ 1) * TILE_F, Bs + (buf ^ 1) * TILE_F, tid);
        const uint32_t* sA = (const uint32_t*)(As + buf * TILE_F);
        const uint32_t* sB = (const uint32_t*)(Bs + buf * TILE_F);
#pragma unroll
        for (int ks = 0; ks < 4; ks++) {
            int k0 = ks * 8;
            uint32_t a[4][4], b[4][2];
#pragma unroll
            for (int mt = 0; mt < 4; mt++) {
                int rb = (warp_m + mt * 16 + g) * SMS + k0 + t;
                a[mt][0] = sA[rb];
                a[mt][1] = sA[rb + 8 * SMS];
                a[mt][2] = sA[rb + 4];
                a[mt][3] = sA[rb + 8 * SMS + 4];
            }
#pragma unroll
            for (int nt = 0; nt < 4; nt++) {
                int rb = (warp_n + nt * 8 + g) * SMS + k0 + t;
                b[nt][0] = sB[rb];
                b[nt][1] = sB[rb + 4];
            }
#pragma unroll
            for (int mt = 0; mt < 4; mt++)
#pragma unroll
                for (int nt = 0; nt < 4; nt++)
                    mma_tf32(acc[mt][nt], a[mt], b[nt]);
        }
        __syncthreads();
    }

#pragma unroll
    for (int mt = 0; mt < 4; mt++) {
#pragma unroll
        for (int half = 0; half < 2; half++) {
            int r = row0 + warp_m + mt * 16 + g + half * 8;
            if (r >= M) continue;
            float* crow = C + (size_t)r * N;
            const float* rrow = (EPI == 2) ? res + (size_t)r * N : nullptr;
#pragma unroll
            for (int nt = 0; nt < 4; nt++) {
                int col = col0 + warp_n + nt * 8 + 2 * t;
                float v0 = acc[mt][nt][half * 2 + 0] + bias[col];
                float v1 = acc[mt][nt][half * 2 + 1] + bias[col + 1];
                if (EPI == 1) {
                    v0 = 0.5f * v0 * (1.f + erff(v0 * 0.70710678118654752f));
                    v1 = 0.5f * v1 * (1.f + erff(v1 * 0.70710678118654752f));
                }
                if (EPI == 2) {
                    v0 += rrow[col];
                    v1 += rrow[col + 1];
                }
                *(float2*)&crow[col] = make_float2(v0, v1);
            }
        }
    }
}

// ---------------- weight transpose: src[K][N] -> dst[N][K], z = layer ------
__global__ void transpose_kernel(const float* __restrict__ src, float* __restrict__ dst,
                                 int K, int N) {
    __shared__ float t[32][33];
    const float* s = src + (size_t)blockIdx.z * K * N;
    float* d = dst + (size_t)blockIdx.z * K * N;
    int k0 = blockIdx.y * 32, n0 = blockIdx.x * 32;
    int x = threadIdx.x, y = threadIdx.y;  // 32 x 8
#pragma unroll
    for (int i = 0; i < 32; i += 8)
        t[y + i][x] = s[(size_t)(k0 + y + i) * N + n0 + x];
    __syncthreads();
#pragma unroll
    for (int i = 0; i < 32; i += 8)
        d[(size_t)(n0 + y + i) * K + k0 + x] = t[x][y + i];
}

// ---------------- LN row stats (mean, rstd) over last dim 768 --------------
__global__ void ln_stats_kernel(const float* __restrict__ x, float eps) {
    int row = blockIdx.x;
    const float* xr = x + (size_t)row * DIM;
    int tid = threadIdx.x;
    float v0 = xr[tid], v1 = xr[tid + 256], v2 = xr[tid + 512];
    float s = v0 + v1 + v2;
    float sq = v0 * v0 + v1 * v1 + v2 * v2;
#pragma unroll
    for (int o = 16; o; o >>= 1) {
        s  += __shfl_xor_sync(0xffffffffu, s, o);
        sq += __shfl_xor_sync(0xffffffffu, sq, o);
    }
    __shared__ float ss[8], ssq[8];
    int w = tid >> 5, l = tid & 31;
    if (l == 0) { ss[w] = s; ssq[w] = sq; }
    __syncthreads();
    if (tid == 0) {
        float ts = 0.f, tq = 0.f;
        for (int i = 0; i < 8; i++) { ts += ss[i]; tq += ssq[i]; }
        float m = ts * (1.f / DIM);
        float var = tq * (1.f / DIM) - m * m;
        g_lnm[row] = m;
        g_lnr[row] = rsqrtf(var + eps);
    }
}

// ---------------- final LN of cls rows only --------------------------------
__global__ void ln_cls_kernel(const float* __restrict__ g, const float* __restrict__ b,
                              float eps) {
    int bb = blockIdx.x;
    const float* xr = g_h + (size_t)bb * NTOK * DIM;  // token 0
    int tid = threadIdx.x;
    float v0 = xr[tid], v1 = xr[tid + 256], v2 = xr[tid + 512];
    float s = v0 + v1 + v2;
    float sq = v0 * v0 + v1 * v1 + v2 * v2;
#pragma unroll
    for (int o = 16; o; o >>= 1) {
        s  += __shfl_xor_sync(0xffffffffu, s, o);
        sq += __shfl_xor_sync(0xffffffffu, sq, o);
    }
    __shared__ float ss[8], ssq[8], red[2];
    int w = tid >> 5, l = tid & 31;
    if (l == 0) { ss[w] = s; ssq[w] = sq; }
    __syncthreads();
    if (tid == 0) {
        float ts = 0.f, tq = 0.f;
        for (int i = 0; i < 8; i++) { ts += ss[i]; tq += ssq[i]; }
        float m = ts * (1.f / DIM);
        float var = tq * (1.f / DIM) - m * m;
        red[0] = m;
        red[1] = rsqrtf(var + eps);
    }
    __syncthreads();
    float m = red[0], r = red[1];
    float* yr = g_cls + bb * DIM;
    yr[tid]       = (v0 - m) * r * g[tid]       + b[tid];
    yr[tid + 256] = (v1 - m) * r * g[tid + 256] + b[tid + 256];
    yr[tid + 512] = (v2 - m) * r * g[tid + 512] + b[tid + 512];
}

// ---------------- fused flash attention ------------------------------------
// grid (10 q-tiles, B*NH), 256 threads. fp32 FFMA, online softmax.
#define ATT_T (64 * 68)
#define ATT_SMEM (4 * ATT_T * 4)   // qs, kst, vs, ps = 69632 B

__global__ void __launch_bounds__(256, 2) attn_fused_kernel() {
    extern __shared__ float asm_[];
    float* qs  = asm_;               // [qi][d]
    float* kst = asm_ + ATT_T;       // [d][kj]
    float* vs  = asm_ + 2 * ATT_T;   // [kj][d]
    float* ps  = asm_ + 3 * ATT_T;   // [qi][kj]
    int z = blockIdx.y;
    int b = z / NH, h = z % NH;
    int qi0 = blockIdx.x * 64;
    int tid = threadIdx.x;
    int ty = tid >> 4, tx = tid & 15;
    int fr = tid >> 4, fc4 = (tid & 15) * 4;
    const float* qbase = g_qkv + (size_t)b * NTOK * QKVW + h * HD;
    const float* kbase = qbase + DIM;
    const float* vbase = qbase + 2 * DIM;

    // load Q tile once
#pragma unroll
    for (int rr = 0; rr < 64; rr += 16) {
        int qn = qi0 + fr + rr;
        float4 v = make_float4(0.f, 0.f, 0.f, 0.f);
        if (qn < NTOK) v = *(const float4*)(qbase + (size_t)qn * QKVW + fc4);
        *(float4*)&qs[(fr + rr) * 68 + fc4] = v;
    }

    float m_i[4], l_i[4], o[4][4];
#pragma unroll
    for (int i = 0; i < 4; i++) {
        m_i[i] = -1e30f;
        l_i[i] = 0.f;
#pragma unroll
        for (int j = 0; j < 4; j++) o[i][j] = 0.f;
    }

    for (int kt = 0; kt < 10; kt++) {
        int kj0 = kt * 64;
        __syncthreads();  // prev PV done before overwriting kst/vs (and Q load on kt=0)
#pragma unroll
        for (int rr = 0; rr < 64; rr += 16) {
            int kn = kj0 + fr + rr;
            float4 kv = make_float4(0.f, 0.f, 0.f, 0.f);
            float4 vv = make_float4(0.f, 0.f, 0.f, 0.f);
            if (kn < NTOK) {
                kv = *(const float4*)(kbase + (size_t)kn * QKVW + fc4);
                vv = *(const float4*)(vbase + (size_t)kn * QKVW + fc4);
            }
            kst[(fc4 + 0) * 68 + fr + rr] = kv.x;
            kst[(fc4 + 1) * 68 + fr + rr] = kv.y;
            kst[(fc4 + 2) * 68 + fr + rr] = kv.z;
            kst[(fc4 + 3) * 68 + fr + rr] = kv.w;
            *(float4*)&vs[(fr + rr) * 68 + fc4] = vv;
        }
        __syncthreads();

        // S = Q K^T
        float s[4][4] = {};
#pragma unroll
        for (int d = 0; d < 64; d++) {
            float a[4], c[4];
#pragma unroll
            for (int i = 0; i < 4; i++) a[i] = qs[(ty * 4 + i) * 68 + d];
#pragma unroll
            for (int j = 0; j < 4; j++) c[j] = kst[d * 68 + tx * 4 + j];
#pragma unroll
            for (int i = 0; i < 4; i++)
#pragma unroll
                for (int j = 0; j < 4; j++)
                    s[i][j] = fmaf(a[i], c[j], s[i][j]);
        }
        // scale + mask invalid kj
#pragma unroll
        for (int j = 0; j < 4; j++) {
            bool valid = (kj0 + tx * 4 + j) < NTOK;
#pragma unroll
            for (int i = 0; i < 4; i++)
                s[i][j] = valid ? s[i][j] * 0.125f : -1e30f;
        }
        // online softmax update (row groups = 16 lanes sharing ty)
#pragma unroll
        for (int i = 0; i < 4; i++) {
            float rmax = fmaxf(fmaxf(s[i][0], s[i][1]), fmaxf(s[i][2], s[i][3]));
#pragma unroll
            for (int off = 8; off; off >>= 1)
                rmax = fmaxf(rmax, __shfl_xor_sync(0xffffffffu, rmax, off));
            float mnew = fmaxf(m_i[i], rmax);
            float scale = expf(m_i[i] - mnew);
            float p0 = expf(s[i][0] - mnew);
            float p1 = expf(s[i][1] - mnew);
            float p2 = expf(s[i][2] - mnew);
            float p3 = expf(s[i][3] - mnew);
            float rsum = p0 + p1 + p2 + p3;
#pragma unroll
            for (int off = 8; off; off >>= 1)
                rsum += __shfl_xor_sync(0xffffffffu, rsum, off);
            l_i[i] = l_i[i] * scale + rsum;
            m_i[i] = mnew;
#pragma unroll
            for (int j = 0; j < 4; j++) o[i][j] *= scale;
            float* prow = &ps[(ty * 4 + i) * 68 + tx * 4];
            prow[0] = p0; prow[1] = p1; prow[2] = p2; prow[3] = p3;
        }
        __syncthreads();
        // O += P @ V
#pragma unroll
        for (int kj = 0; kj < 64; kj++) {
            float a[4], c[4];
#pragma unroll
            for (int i = 0; i < 4; i++) a[i] = ps[(ty * 4 + i) * 68 + kj];
#pragma unroll
            for (int j = 0; j < 4; j++) c[j] = vs[kj * 68 + tx * 4 + j];
#pragma unroll
            for (int i = 0; i < 4; i++)
#pragma unroll
                for (int j = 0; j < 4; j++)
                    o[i][j] = fmaf(a[i], c[j], o[i][j]);
        }
    }

#pragma unroll
    for (int i = 0; i < 4; i++) {
        int qi = qi0 + ty * 4 + i;
        if (qi >= NTOK) continue;
        float inv = 1.f / l_i[i];
        float* orow = g_o + ((size_t)b * NTOK + qi) * DIM + h * HD;
#pragma unroll
        for (int j = 0; j < 4; j++) orow[tx * 4 + j] = o[i][j] * inv;
    }
}

// ---------------- patch embed helpers --------------------------------------
__global__ void extract_patches_kernel(const float* __restrict__ x) {
    int idx = blockIdx.x * blockDim.x + threadIdx.x;
    if (idx >= BATCH * NPATCH * DIM) return;
    int f = idx % DIM;
    int p = (idx / DIM) % NPATCH;
    int b = idx / (DIM * NPATCH);
    int gy = p / 24, gx = p % 24;
    int c = f >> 8;
    int rem = f & 255;
    int py = rem >> 4, px = rem & 15;
    g_patches[idx] = x[(((size_t)b * 3 + c) * 384 + gy * 16 + py) * 384 + gx * 16 + px];
}

__global__ void embed_kernel(const float* __restrict__ cls, const float* __restrict__ pos) {
    int idx = blockIdx.x * blockDim.x + threadIdx.x;
    if (idx >= ROWS * DIM) return;
    int d = idx % DIM;
    int t = (idx / DIM) % NTOK;
    int b = idx / (DIM * NTOK);
    float v = (t == 0) ? cls[d] : g_tmp[((size_t)b * NPATCH + (t - 1)) * DIM + d];
    g_h[idx] = v + pos[t * DIM + d];
}

// ---------------- classification head --------------------------------------
__global__ void head_kernel(const float* __restrict__ hw, const float* __restrict__ hb,
                            float* __restrict__ out) {
    __shared__ float xs[DIM];
    int b = blockIdx.y;
    int tid = threadIdx.x;
    const float* xr = g_cls + b * DIM;
    xs[tid] = xr[tid];
    xs[tid + 256] = xr[tid + 256];
    xs[tid + 512] = xr[tid + 512];
    __syncthreads();
    int c = blockIdx.x * 256 + tid;
    if (c < NCLS) {
        float acc = hb[c];
        for (int d = 0; d < DIM; d++)
            acc = fmaf(xs[d], hw[(size_t)d * NCLS + c], acc);
        out[b * NCLS + c] = acc;
    }
}

// ---------------- launch ----------------------------------------------------
extern "C" void kernel_launch(void* const* d_in, const int* in_sizes, int n_in,
                              void* d_out, int out_size) {
    const float* x       = (const float*)d_in[0];
    const float* patch_w = (const float*)d_in[1];
    const float* patch_b = (const float*)d_in[2];
    const float* cls_tok = (const float*)d_in[3];
    const float* pos_emb = (const float*)d_in[4];
    const float* ln1_g   = (const float*)d_in[5];
    const float* ln1_b   = (const float*)d_in[6];
    const float* qkv_w   = (const float*)d_in[7];
    const float* qkv_b   = (const float*)d_in[8];
    const float* proj_w  = (const float*)d_in[9];
    const float* proj_b  = (const float*)d_in[10];
    const float* ln2_g   = (const float*)d_in[11];
    const float* ln2_b   = (const float*)d_in[12];
    const float* mlp_w1  = (const float*)d_in[13];
    const float* mlp_b1  = (const float*)d_in[14];
    const float* mlp_w2  = (const float*)d_in[15];
    const float* mlp_b2  = (const float*)d_in[16];
    const float* lnf_g   = (const float*)d_in[17];
    const float* lnf_b   = (const float*)d_in[18];
    const float* head_w  = (const float*)d_in[19];
    const float* head_b  = (const float*)d_in[20];
    float* out = (float*)d_out;

    float *h_, *qkv_, *o_, *mid_, *pat_, *tmp_;
    float *qkvT_, *projT_, *w1T_, *w2T_;
    cudaGetSymbolAddress((void**)&h_, g_h);
    cudaGetSymbolAddress((void**)&qkv_, g_qkv);
    cudaGetSymbolAddress((void**)&o_, g_o);
    cudaGetSymbolAddress((void**)&mid_, g_mid);
    cudaGetSymbolAddress((void**)&pat_, g_patches);
    cudaGetSymbolAddress((void**)&tmp_, g_tmp);
    cudaGetSymbolAddress((void**)&qkvT_, g_qkvT);
    cudaGetSymbolAddress((void**)&projT_, g_projT);
    cudaGetSymbolAddress((void**)&w1T_, g_w1T);
    cudaGetSymbolAddress((void**)&w2T_, g_w2T);

    cudaFuncSetAttribute(gemm_mma<0, false>, cudaFuncAttributeMaxDynamicSharedMemorySize, GEMM_SMEM);
    cudaFuncSetAttribute(gemm_mma<0, true>,  cudaFuncAttributeMaxDynamicSharedMemorySize, GEMM_SMEM);
    cudaFuncSetAttribute(gemm_mma<1, true>,  cudaFuncAttributeMaxDynamicSharedMemorySize, GEMM_SMEM);
    cudaFuncSetAttribute(gemm_mma<2, false>, cudaFuncAttributeMaxDynamicSharedMemorySize, GEMM_SMEM);
    cudaFuncSetAttribute(attn_fused_kernel,  cudaFuncAttributeMaxDynamicSharedMemorySize, ATT_SMEM);

    // Weight transposes ([K][N] -> [N][K]) once per launch
    dim3 tb(32, 8);
    transpose_kernel<<<dim3(QKVW / 32, DIM / 32, DEPTH), tb>>>(qkv_w, qkvT_, DIM, QKVW);
    transpose_kernel<<<dim3(DIM / 32, DIM / 32, DEPTH), tb>>>(proj_w, projT_, DIM, DIM);
    transpose_kernel<<<dim3(HID / 32, DIM / 32, DEPTH), tb>>>(mlp_w1, w1T_, DIM, HID);
    transpose_kernel<<<dim3(DIM / 32, HID / 32, DEPTH), tb>>>(mlp_w2, w2T_, HID, DIM);

    // Patch embedding
    extract_patches_kernel<<<(BATCH * NPATCH * DIM + 255) / 256, 256>>>(x);
    gemm_mma<0, false><<<dim3(DIM / 128, (BATCH * NPATCH) / 128), 256, GEMM_SMEM>>>(
        pat_, patch_w, patch_b, nullptr, nullptr, nullptr, tmp_, BATCH * NPATCH, DIM, DIM);
    embed_kernel<<<(ROWS * DIM + 255) / 256, 256>>>(cls_tok, pos_emb);

    const int MG = (ROWS + 127) / 128;  // 37

    for (int l = 0; l < DEPTH; l++) {
        ln_stats_kernel<<<ROWS, 256>>>(h_, 1e-5f);
        gemm_mma<0, true><<<dim3(QKVW / 128, MG), 256, GEMM_SMEM>>>(
            h_, qkvT_ + (size_t)l * QKVW * DIM, qkv_b + (size_t)l * QKVW,
            nullptr, ln1_g + l * DIM, ln1_b + l * DIM, qkv_, ROWS, QKVW, DIM);
        attn_fused_kernel<<<dim3(10, BATCH * NH), 256, ATT_SMEM>>>();
        gemm_mma<2, false><<<dim3(DIM / 128, MG), 256, GEMM_SMEM>>>(
            o_, projT_ + (size_t)l * DIM * DIM, proj_b + (size_t)l * DIM,
            h_, nullptr, nullptr, h_, ROWS, DIM, DIM);
        ln_stats_kernel<<<ROWS, 256>>>(h_, 1e-5f);
        gemm_mma<1, true><<<dim3(HID / 128, MG), 256, GEMM_SMEM>>>(
            h_, w1T_ + (size_t)l * HID * DIM, mlp_b1 + (size_t)l * HID,
            nullptr, ln2_g + l * DIM, ln2_b + l * DIM, mid_, ROWS, HID, DIM);
        gemm_mma<2, false><<<dim3(DIM / 128, MG), 256, GEMM_SMEM>>>(
            mid_, w2T_ + (size_t)l * DIM * HID, mlp_b2 + (size_t)l * DIM,
            h_, nullptr, nullptr, h_, ROWS, DIM, HID);
    }

    ln_cls_kernel<<<BATCH, 256>>>(lnf_g, lnf_b, 1e-6f);
    head_kernel<<<dim3(4, BATCH), 256>>>(head_w, head_b, out);
}